// round 8
// baseline (speedup 1.0000x reference)
#include <cuda_runtime.h>
#include <math.h>
#include <stdint.h>

// Problem dims
#define SEQ   2048
#define DIN   2048
#define NH    16
#define NG    4
#define GSZ   4
#define HD    128
#define NTOK  4096
#define QSCALE 0.08838834764831843f   // 128^-0.5

// ---------------- scratch (device globals; no allocation allowed) -------------
__device__ float g_q[(size_t)NTOK * (NH * HD)];
__device__ float g_k[(size_t)NTOK * (NG * HD)];
__device__ float g_v[(size_t)NTOK * (NG * HD)];
__device__ float g_ctx[(size_t)NTOK * (NH * HD)];

__device__ __forceinline__ uint32_t f2tf32(float x) {
    uint32_t u;
    asm("cvt.rna.tf32.f32 %0, %1;" : "=r"(u) : "f"(x));
    return u;
}

#define MMA_TF32(d, a, b0, b1)                                              \
    asm volatile(                                                           \
        "mma.sync.aligned.m16n8k8.row.col.f32.tf32.tf32.f32 "               \
        "{%0,%1,%2,%3}, {%4,%5,%6,%7}, {%8,%9}, {%0,%1,%2,%3};"             \
        : "+f"(d[0]), "+f"(d[1]), "+f"(d[2]), "+f"(d[3])                    \
        : "r"(a[0]), "r"(a[1]), "r"(a[2]), "r"(a[3]), "r"(b0), "r"(b1))

// =============================================================================
// TF32 tensor-core GEMM core: C[M,N] = A[M,K] @ B[K,N], row-major fp32.
// BM=BN=128, BK=64, 512 threads = 16 warps (4M x 4N), warp tile 32x32.
// Double-buffered smem, register prefetch, rna tf32 conversion at staging.
// A smem: m-major stride 68  (==4 mod 32): a-frag bank (4r+c)%32 distinct.
// B smem: k-major stride 136 (==8 mod 32): b-frag bank (8c+r)%32 distinct.
// =============================================================================
#define AS_STRIDE 68
#define BS_STRIDE 136
#define AS_ELEMS (128 * AS_STRIDE)   // 8704 floats
#define BS_ELEMS (64 * BS_STRIDE)    // 8704 floats
#define GEMM_SMEM ((2 * AS_ELEMS + 2 * BS_ELEMS) * 4)   // 139264 bytes

__device__ __forceinline__ void store_chunkA(float* dst, const float4* ra, int tid) {
#pragma unroll
    for (int i = 0; i < 4; i++) {
        int idx = tid + i * 512;
        int row = idx >> 4, kc = (idx & 15) * 4;
        float4 v = ra[i];
        float4 w;
        w.x = __uint_as_float(f2tf32(v.x));
        w.y = __uint_as_float(f2tf32(v.y));
        w.z = __uint_as_float(f2tf32(v.z));
        w.w = __uint_as_float(f2tf32(v.w));
        *(float4*)(&dst[row * AS_STRIDE + kc]) = w;
    }
}
__device__ __forceinline__ void store_chunkB(float* dst, const float4* rb, int tid) {
#pragma unroll
    for (int i = 0; i < 4; i++) {
        int idx = tid + i * 512;
        int k = idx >> 5, nc = (idx & 31) * 4;
        float4 v = rb[i];
        float4 w;
        w.x = __uint_as_float(f2tf32(v.x));
        w.y = __uint_as_float(f2tf32(v.y));
        w.z = __uint_as_float(f2tf32(v.z));
        w.w = __uint_as_float(f2tf32(v.w));
        *(float4*)(&dst[k * BS_STRIDE + nc]) = w;
    }
}

__device__ __forceinline__ void gemm_core(
    const float* __restrict__ gA, const float* __restrict__ gB,
    float* __restrict__ gC, int N, int K, float* smbase)
{
    float* As = smbase;
    float* Bs = smbase + 2 * AS_ELEMS;

    const int tid  = threadIdx.x;
    const int wid  = tid >> 5;
    const int lane = tid & 31;
    const int r = lane >> 2;
    const int c = lane & 3;
    const int warp_m = wid >> 2;     // 0..3 (32 rows each)
    const int warp_n = wid & 3;      // 0..3 (32 cols each)

    float acc[2][4][4];
#pragma unroll
    for (int mt = 0; mt < 2; mt++)
#pragma unroll
        for (int nt = 0; nt < 4; nt++)
#pragma unroll
            for (int x = 0; x < 4; x++) acc[mt][nt][x] = 0.f;

    float4 ra[4], rb[4];
    const int nIt = K / 64;

#pragma unroll
    for (int i = 0; i < 4; i++) {
        int idx = tid + i * 512;
        ra[i] = *(const float4*)(gA + (size_t)(idx >> 4) * K + ((idx & 15) * 4));
        rb[i] = *(const float4*)(gB + (size_t)(idx >> 5) * N + ((idx & 31) * 4));
    }
    store_chunkA(As, ra, tid);
    store_chunkB(Bs, rb, tid);
    __syncthreads();

    for (int it = 0; it < nIt; it++) {
        const int buf = it & 1;
        if (it + 1 < nIt) {
            const int k0 = (it + 1) * 64;
#pragma unroll
            for (int i = 0; i < 4; i++) {
                int idx = tid + i * 512;
                ra[i] = *(const float4*)(gA + (size_t)(idx >> 4) * K + k0 + ((idx & 15) * 4));
                rb[i] = *(const float4*)(gB + (size_t)(k0 + (idx >> 5)) * N + ((idx & 31) * 4));
            }
        }

        const float* a_s = As + buf * AS_ELEMS;
        const float* b_s = Bs + buf * BS_ELEMS;

#pragma unroll
        for (int ks = 0; ks < 8; ks++) {
            const int kc = ks * 8 + c;
            uint32_t af[2][4];
#pragma unroll
            for (int mt = 0; mt < 2; mt++) {
                const int row0 = warp_m * 32 + mt * 16 + r;
                af[mt][0] = __float_as_uint(a_s[row0 * AS_STRIDE + kc]);
                af[mt][1] = __float_as_uint(a_s[(row0 + 8) * AS_STRIDE + kc]);
                af[mt][2] = __float_as_uint(a_s[row0 * AS_STRIDE + kc + 4]);
                af[mt][3] = __float_as_uint(a_s[(row0 + 8) * AS_STRIDE + kc + 4]);
            }
#pragma unroll
            for (int nt = 0; nt < 4; nt++) {
                const int n0 = warp_n * 32 + nt * 8 + r;
                uint32_t b0 = __float_as_uint(b_s[kc * BS_STRIDE + n0]);
                uint32_t b1 = __float_as_uint(b_s[(kc + 4) * BS_STRIDE + n0]);
                MMA_TF32(acc[0][nt], af[0], b0, b1);
                MMA_TF32(acc[1][nt], af[1], b0, b1);
            }
        }

        if (it + 1 < nIt) {
            const int nbuf = buf ^ 1;
            __syncthreads();
            store_chunkA(As + nbuf * AS_ELEMS, ra, tid);
            store_chunkB(Bs + nbuf * BS_ELEMS, rb, tid);
            __syncthreads();
        }
    }

#pragma unroll
    for (int mt = 0; mt < 2; mt++) {
#pragma unroll
        for (int nt = 0; nt < 4; nt++) {
            const int row0 = warp_m * 32 + mt * 16 + r;
            const int col  = warp_n * 32 + nt * 8 + 2 * c;
            *(float2*)(gC + (size_t)row0 * N + col) =
                make_float2(acc[mt][nt][0], acc[mt][nt][1]);
            *(float2*)(gC + (size_t)(row0 + 8) * N + col) =
                make_float2(acc[mt][nt][2], acc[mt][nt][3]);
        }
    }
}

// plain GEMM (used for Wo)
__global__ __launch_bounds__(512, 1) void tf32_gemm(
    const float* __restrict__ A, const float* __restrict__ B,
    float* __restrict__ C, int N, int K)
{
    extern __shared__ float sm[];
    const int bx = blockIdx.x, by = blockIdx.y;
    gemm_core(A + (size_t)(by * 128) * K, B + bx * 128,
              C + (size_t)(by * 128) * N + bx * 128, N, K, sm);
}

// fused QKV projection: grid.x = 16 (Q tiles) + 4 (K) + 4 (V), grid.y = M/128
__global__ __launch_bounds__(512, 1) void tf32_gemm_qkv(
    const float* __restrict__ x,
    const float* __restrict__ Wq, const float* __restrict__ Wk,
    const float* __restrict__ Wv,
    float* __restrict__ q, float* __restrict__ k, float* __restrict__ v)
{
    extern __shared__ float sm[];
    const int bx = blockIdx.x, by = blockIdx.y;
    const float* B;
    float* C;
    int N, xb;
    if (bx < 16)      { B = Wq; C = q; N = 2048; xb = bx; }
    else if (bx < 20) { B = Wk; C = k; N = 512;  xb = bx - 16; }
    else              { B = Wv; C = v; N = 512;  xb = bx - 20; }
    gemm_core(x + (size_t)(by * 128) * DIN, B + xb * 128,
              C + (size_t)(by * 128) * N + xb * 128, N, DIN, sm);
}

// ---------------- fused RMSNorm + RoPE, q & k in one launch ------------------
__global__ __launch_bounds__(128) void rmsrope_kernel(
    float* __restrict__ q, float* __restrict__ k,
    const float* __restrict__ qw, const float* __restrict__ kw,
    const float* __restrict__ cosb, const float* __restrict__ sinb)
{
    const int tok = blockIdx.x;
    const int hy = blockIdx.y;
    const int d = threadIdx.x;
    const int s = tok & (SEQ - 1);

    float* p;
    const float* w;
    float outscale;
    if (hy < NH) {
        p = q + (size_t)tok * (NH * HD) + hy * HD;
        w = qw;
        outscale = QSCALE;
    } else {
        p = k + (size_t)tok * (NG * HD) + (hy - NH) * HD;
        w = kw;
        outscale = 1.0f;
    }
    float v = p[d];

    float ss = v * v;
#pragma unroll
    for (int o = 16; o > 0; o >>= 1) ss += __shfl_xor_sync(0xffffffffu, ss, o);

    __shared__ float partial[4];
    __shared__ float sn[HD];
    if ((d & 31) == 0) partial[d >> 5] = ss;
    __syncthreads();
    float tot = partial[0] + partial[1] + partial[2] + partial[3];
    float rstd = rsqrtf(tot * (1.0f / HD) + 1e-6f);

    float nv = v * rstd * w[d];
    sn[d] = nv;
    __syncthreads();
    float other = sn[d ^ 64];

    float cc = cosb[(size_t)s * HD + d];
    float si = sinb[(size_t)s * HD + d];
    float outv = (d < 64) ? (nv * cc - other * si) : (nv * cc + other * si);
    p[d] = outv * outscale;
}

// =============================================================================
// Tensor-core causal GQA flash attention (tf32 mma.sync) — unchanged.
// =============================================================================
#define A_BQ 128
#define A_BK 64
#define QST 132
#define KST 132
#define VST 136
#define PST 68
#define SK_OFF (128 * QST)
#define SV_OFF (SK_OFF + 64 * KST)
#define SP_OFF (SV_OFF + 64 * VST)
#define ATTN_SMEM ((SP_OFF + 128 * PST) * 4)

__global__ __launch_bounds__(256, 1) void attn_tc_kernel(
    const float* __restrict__ q, const float* __restrict__ k,
    const float* __restrict__ v, float* __restrict__ out)
{
    extern __shared__ float smf[];
    float* sQ = smf;
    float* sK = smf + SK_OFF;
    float* sV = smf + SV_OFF;
    float* sP = smf + SP_OFF;

    const int tid  = threadIdx.x;
    const int wid  = tid >> 5;
    const int lane = tid & 31;
    const int r = lane >> 2;
    const int c = lane & 3;
    const int wm = wid;

    const int qt = gridDim.x - 1 - blockIdx.x;
    const int h  = blockIdx.y;
    const int b  = blockIdx.z;
    const int g  = h >> 2;
    const int qbase = qt * A_BQ;

    const float* qp = q + (size_t)b * SEQ * (NH * HD) + h * HD;
    const float* kp = k + (size_t)b * SEQ * (NG * HD) + g * HD;
    const float* vp = v + (size_t)b * SEQ * (NG * HD) + g * HD;

#pragma unroll
    for (int i = 0; i < 16; i++) {
        int idx = tid + i * 256;
        int row = idx >> 5, c4 = (idx & 31) * 4;
        float4 v4 = *(const float4*)(qp + (size_t)(qbase + row) * (NH * HD) + c4);
        float4 w4;
        w4.x = __uint_as_float(f2tf32(v4.x));
        w4.y = __uint_as_float(f2tf32(v4.y));
        w4.z = __uint_as_float(f2tf32(v4.z));
        w4.w = __uint_as_float(f2tf32(v4.w));
        *(float4*)(&sQ[row * QST + c4]) = w4;
    }

    float o[16][4];
#pragma unroll
    for (int nt = 0; nt < 16; nt++)
#pragma unroll
        for (int x = 0; x < 4; x++) o[nt][x] = 0.f;
    float m0 = -1e30f, m1 = -1e30f, l0 = 0.f, l1 = 0.f;

    const int row0g = qbase + wm * 16 + r;
    const int row1g = row0g + 8;

    const int ntiles = 2 * qt + 2;
    for (int kt = 0; kt < ntiles; kt++) {
        const int kbase = kt * A_BK;
        __syncthreads();
#pragma unroll
        for (int i = 0; i < 8; i++) {
            int idx = tid + i * 256;
            int row = idx >> 5, c4 = (idx & 31) * 4;
            float4 k4 = *(const float4*)(kp + (size_t)(kbase + row) * (NG * HD) + c4);
            float4 v4 = *(const float4*)(vp + (size_t)(kbase + row) * (NG * HD) + c4);
            float4 kw, vw;
            kw.x = __uint_as_float(f2tf32(k4.x));
            kw.y = __uint_as_float(f2tf32(k4.y));
            kw.z = __uint_as_float(f2tf32(k4.z));
            kw.w = __uint_as_float(f2tf32(k4.w));
            vw.x = __uint_as_float(f2tf32(v4.x));
            vw.y = __uint_as_float(f2tf32(v4.y));
            vw.z = __uint_as_float(f2tf32(v4.z));
            vw.w = __uint_as_float(f2tf32(v4.w));
            *(float4*)(&sK[row * KST + c4]) = kw;
            *(float4*)(&sV[row * VST + c4]) = vw;
        }
        __syncthreads();

        if (qbase + wm * 16 + 15 < kbase) continue;

        float sc[8][4];
#pragma unroll
        for (int nt = 0; nt < 8; nt++)
#pragma unroll
            for (int x = 0; x < 4; x++) sc[nt][x] = 0.f;

#pragma unroll
        for (int kk = 0; kk < 16; kk++) {
            const int kc = kk * 8 + c;
            uint32_t a[4];
            a[0] = __float_as_uint(sQ[(wm * 16 + r) * QST + kc]);
            a[1] = __float_as_uint(sQ[(wm * 16 + r + 8) * QST + kc]);
            a[2] = __float_as_uint(sQ[(wm * 16 + r) * QST + kc + 4]);
            a[3] = __float_as_uint(sQ[(wm * 16 + r + 8) * QST + kc + 4]);
#pragma unroll
            for (int nt = 0; nt < 8; nt++) {
                uint32_t b0 = __float_as_uint(sK[(nt * 8 + r) * KST + kc]);
                uint32_t b1 = __float_as_uint(sK[(nt * 8 + r) * KST + kc + 4]);
                MMA_TF32(sc[nt], a, b0, b1);
            }
        }

        if (kbase + 63 > qbase + wm * 16) {
#pragma unroll
            for (int nt = 0; nt < 8; nt++) {
                int col = kbase + nt * 8 + 2 * c;
                if (col     > row0g) sc[nt][0] = -1e30f;
                if (col + 1 > row0g) sc[nt][1] = -1e30f;
                if (col     > row1g) sc[nt][2] = -1e30f;
                if (col + 1 > row1g) sc[nt][3] = -1e30f;
            }
        }

        float tm0 = -1e30f, tm1 = -1e30f;
#pragma unroll
        for (int nt = 0; nt < 8; nt++) {
            tm0 = fmaxf(tm0, fmaxf(sc[nt][0], sc[nt][1]));
            tm1 = fmaxf(tm1, fmaxf(sc[nt][2], sc[nt][3]));
        }
        tm0 = fmaxf(tm0, __shfl_xor_sync(0xffffffffu, tm0, 1));
        tm0 = fmaxf(tm0, __shfl_xor_sync(0xffffffffu, tm0, 2));
        tm1 = fmaxf(tm1, __shfl_xor_sync(0xffffffffu, tm1, 1));
        tm1 = fmaxf(tm1, __shfl_xor_sync(0xffffffffu, tm1, 2));
        float nm0 = fmaxf(m0, tm0);
        float nm1 = fmaxf(m1, tm1);
        float al0 = __expf(m0 - nm0);
        float al1 = __expf(m1 - nm1);
        float ts0 = 0.f, ts1 = 0.f;
#pragma unroll
        for (int nt = 0; nt < 8; nt++) {
            sc[nt][0] = __expf(sc[nt][0] - nm0);
            sc[nt][1] = __expf(sc[nt][1] - nm0);
            sc[nt][2] = __expf(sc[nt][2] - nm1);
            sc[nt][3] = __expf(sc[nt][3] - nm1);
            ts0 += sc[nt][0] + sc[nt][1];
            ts1 += sc[nt][2] + sc[nt][3];
        }
        ts0 += __shfl_xor_sync(0xffffffffu, ts0, 1);
        ts0 += __shfl_xor_sync(0xffffffffu, ts0, 2);
        ts1 += __shfl_xor_sync(0xffffffffu, ts1, 1);
        ts1 += __shfl_xor_sync(0xffffffffu, ts1, 2);
        l0 = l0 * al0 + ts0;
        l1 = l1 * al1 + ts1;
        m0 = nm0;
        m1 = nm1;
#pragma unroll
        for (int nt = 0; nt < 16; nt++) {
            o[nt][0] *= al0;
            o[nt][1] *= al0;
            o[nt][2] *= al1;
            o[nt][3] *= al1;
        }

#pragma unroll
        for (int nt = 0; nt < 8; nt++) {
            *(float2*)(&sP[(wm * 16 + r) * PST + nt * 8 + 2 * c]) =
                make_float2(sc[nt][0], sc[nt][1]);
            *(float2*)(&sP[(wm * 16 + r + 8) * PST + nt * 8 + 2 * c]) =
                make_float2(sc[nt][2], sc[nt][3]);
        }
        __syncwarp();

#pragma unroll
        for (int kk = 0; kk < 8; kk++) {
            const int kc = kk * 8 + c;
            uint32_t pa[4];
            pa[0] = __float_as_uint(sP[(wm * 16 + r) * PST + kc]);
            pa[1] = __float_as_uint(sP[(wm * 16 + r + 8) * PST + kc]);
            pa[2] = __float_as_uint(sP[(wm * 16 + r) * PST + kc + 4]);
            pa[3] = __float_as_uint(sP[(wm * 16 + r + 8) * PST + kc + 4]);
#pragma unroll
            for (int nt = 0; nt < 16; nt++) {
                uint32_t b0 = __float_as_uint(sV[kc * VST + nt * 8 + r]);
                uint32_t b1 = __float_as_uint(sV[(kc + 4) * VST + nt * 8 + r]);
                MMA_TF32(o[nt], pa, b0, b1);
            }
        }
    }

    const float inv0 = 1.0f / l0;
    const float inv1 = 1.0f / l1;
#pragma unroll
    for (int nt = 0; nt < 16; nt++) {
        const int col = h * HD + nt * 8 + 2 * c;
        *(float2*)(out + (size_t)((size_t)b * SEQ + row0g) * (NH * HD) + col) =
            make_float2(o[nt][0] * inv0, o[nt][1] * inv0);
        *(float2*)(out + (size_t)((size_t)b * SEQ + row1g) * (NH * HD) + col) =
            make_float2(o[nt][2] * inv1, o[nt][3] * inv1);
    }
}

// ---------------- launch -----------------------------------------------------
extern "C" void kernel_launch(void* const* d_in, const int* in_sizes, int n_in,
                              void* d_out, int out_size)
{
    const float* x    = (const float*)d_in[0];
    // d_in[1] = mask (causal, implicit)
    const float* cosb = (const float*)d_in[2];
    const float* sinb = (const float*)d_in[3];
    const float* Wq   = (const float*)d_in[4];
    const float* Wk   = (const float*)d_in[5];
    const float* Wv   = (const float*)d_in[6];
    const float* Wo   = (const float*)d_in[7];
    const float* qw   = (const float*)d_in[8];
    const float* kw   = (const float*)d_in[9];
    float* out = (float*)d_out;

    void *qp, *kp, *vp, *cp;
    cudaGetSymbolAddress(&qp, g_q);
    cudaGetSymbolAddress(&kp, g_k);
    cudaGetSymbolAddress(&vp, g_v);
    cudaGetSymbolAddress(&cp, g_ctx);

    cudaFuncSetAttribute(tf32_gemm, cudaFuncAttributeMaxDynamicSharedMemorySize, GEMM_SMEM);
    cudaFuncSetAttribute(tf32_gemm_qkv, cudaFuncAttributeMaxDynamicSharedMemorySize, GEMM_SMEM);
    cudaFuncSetAttribute(attn_tc_kernel, cudaFuncAttributeMaxDynamicSharedMemorySize, ATTN_SMEM);

    // fused QKV projection (tf32 tensor cores)
    tf32_gemm_qkv<<<dim3(24, NTOK / 128), 512, GEMM_SMEM>>>(
        x, Wq, Wk, Wv, (float*)qp, (float*)kp, (float*)vp);

    // fused RMSNorm + RoPE for q and k in one launch
    rmsrope_kernel<<<dim3(NTOK, NH + NG), 128>>>(
        (float*)qp, (float*)kp, qw, kw, cosb, sinb);

    // tensor-core flash attention
    attn_tc_kernel<<<dim3(SEQ / A_BQ, NH, 2), 256, ATTN_SMEM>>>(
        (const float*)qp, (const float*)kp, (const float*)vp, (float*)cp);

    // output projection
    tf32_gemm<<<dim3(DIN / 128, NTOK / 128), 512, GEMM_SMEM>>>(
        (const float*)cp, Wo, out, DIN, DIN);
}

// round 13
// speedup vs baseline: 1.1690x; 1.1690x over previous
#include <cuda_runtime.h>
#include <math.h>
#include <stdint.h>

// Problem dims
#define SEQ   2048
#define DIN   2048
#define NH    16
#define NG    4
#define GSZ   4
#define HD    128
#define NTOK  4096
#define QSCALE 0.08838834764831843f   // 128^-0.5

// ---------------- scratch (device globals; no allocation allowed) -------------
__device__ float g_q[(size_t)NTOK * (NH * HD)];
__device__ float g_k[(size_t)NTOK * (NG * HD)];
__device__ float g_v[(size_t)NTOK * (NG * HD)];
__device__ float g_ctx[(size_t)NTOK * (NH * HD)];
// tf32-rounded copies (prep)
__device__ float g_xr[(size_t)NTOK * DIN];
__device__ float g_wqr[(size_t)DIN * DIN];
__device__ float g_wkr[(size_t)DIN * 512];
__device__ float g_wvr[(size_t)DIN * 512];
__device__ float g_wor[(size_t)DIN * DIN];

__device__ __forceinline__ uint32_t f2tf32(float x) {
    uint32_t u;
    asm("cvt.rna.tf32.f32 %0, %1;" : "=r"(u) : "f"(x));
    return u;
}

#define MMA_TF32(d, a, b0, b1)                                              \
    asm volatile(                                                           \
        "mma.sync.aligned.m16n8k8.row.col.f32.tf32.tf32.f32 "               \
        "{%0,%1,%2,%3}, {%4,%5,%6,%7}, {%8,%9}, {%0,%1,%2,%3};"             \
        : "+f"(d[0]), "+f"(d[1]), "+f"(d[2]), "+f"(d[3])                    \
        : "r"(a[0]), "r"(a[1]), "r"(a[2]), "r"(a[3]), "r"(b0), "r"(b1))

__device__ __forceinline__ uint32_t smem_u32_of(const void* p) {
    uint32_t a;
    asm("{ .reg .u64 t; cvta.to.shared.u64 t, %1; cvt.u32.u64 %0, t; }"
        : "=r"(a) : "l"(p));
    return a;
}
__device__ __forceinline__ void cpasync16(uint32_t dst, const void* src) {
    asm volatile("cp.async.cg.shared.global [%0], [%1], 16;" :: "r"(dst), "l"(src));
}
#define CP_COMMIT() asm volatile("cp.async.commit_group;" ::: "memory")
#define CP_WAIT2()  asm volatile("cp.async.wait_group 2;" ::: "memory")

// =============================================================================
// TF32 tensor-core GEMM: C[M,N] = A[M,K] @ B[K,N], row-major, inputs already
// tf32-rounded fp32. CTA tile 256x128, BK=32, 256 threads = 8 warps (4M x 2N),
// warp tile 64x64 (fragment-LDS : mma = 1:1). 4-stage cp.async pipeline.
// A smem: m-major stride 36  (==4 mod 32): a-frag bank (4r+c)%32 distinct.
// B smem: k-major stride 136 (==8 mod 32): b-frag bank (8c+r)%32 distinct.
// =============================================================================
#define BMM 256
#define BNN 128
#define BKK 32
#define AST 36
#define BST 136
#define ASE (BMM * AST)             // 9216 floats
#define BSE (BKK * BST)             // 4352 floats
#define STG_STRIDE ((ASE + BSE) * 4)  // 54272 bytes, 16B-aligned
#define GEMM_SMEM (4 * STG_STRIDE)    // 217088 bytes

__device__ __forceinline__ void gemm_issue(
    uint32_t smbase, int buf, const float* gA, const float* gB,
    int k0, int N, int K, int tid)
{
    const uint32_t aB = smbase + buf * STG_STRIDE;
    const uint32_t bB = aB + ASE * 4;
#pragma unroll
    for (int i = 0; i < 8; i++) {
        int quad = tid + i * 256;
        int row = quad >> 3, c16 = quad & 7;
        cpasync16(aB + row * (AST * 4) + c16 * 16,
                  gA + (size_t)row * K + k0 + c16 * 4);
    }
#pragma unroll
    for (int i = 0; i < 4; i++) {
        int quad = tid + i * 256;
        int kr = quad >> 5, nq = quad & 31;
        cpasync16(bB + kr * (BST * 4) + nq * 16,
                  gB + (size_t)(k0 + kr) * N + nq * 4);
    }
}

__device__ __forceinline__ void gemm_core(
    const float* __restrict__ gA, const float* __restrict__ gB,
    float* __restrict__ gC, int N, int K, char* smc)
{
    const int tid  = threadIdx.x;
    const int wid  = tid >> 5;
    const int lane = tid & 31;
    const int r = lane >> 2;
    const int c = lane & 3;
    const int wm = wid >> 1;     // 0..3 (64 rows each)
    const int wn = wid & 1;      // 0..1 (64 cols each)
    const uint32_t smbase = smem_u32_of(smc);

    float acc[4][8][4];
#pragma unroll
    for (int mt = 0; mt < 4; mt++)
#pragma unroll
        for (int nt = 0; nt < 8; nt++)
#pragma unroll
            for (int x = 0; x < 4; x++) acc[mt][nt][x] = 0.f;

    const int nIt = K / BKK;

    // prologue: stages 0..2
#pragma unroll
    for (int s = 0; s < 3; s++) {
        gemm_issue(smbase, s, gA, gB, s * BKK, N, K, tid);
        CP_COMMIT();
    }

    for (int it = 0; it < nIt; it++) {
        CP_WAIT2();
        __syncthreads();

        if (it + 3 < nIt)
            gemm_issue(smbase, (it + 3) & 3, gA, gB, (it + 3) * BKK, N, K, tid);
        CP_COMMIT();

        const float* a_s = (const float*)(smc + (it & 3) * STG_STRIDE);
        const float* b_s = a_s + ASE;

#pragma unroll
        for (int ks = 0; ks < 4; ks++) {
            const int kc = ks * 8 + c;
            uint32_t af[4][4];
#pragma unroll
            for (int mt = 0; mt < 4; mt++) {
                const int row0 = wm * 64 + mt * 16 + r;
                af[mt][0] = __float_as_uint(a_s[row0 * AST + kc]);
                af[mt][1] = __float_as_uint(a_s[(row0 + 8) * AST + kc]);
                af[mt][2] = __float_as_uint(a_s[row0 * AST + kc + 4]);
                af[mt][3] = __float_as_uint(a_s[(row0 + 8) * AST + kc + 4]);
            }
#pragma unroll
            for (int nt = 0; nt < 8; nt++) {
                const int n0 = wn * 64 + nt * 8 + r;
                uint32_t b0 = __float_as_uint(b_s[kc * BST + n0]);
                uint32_t b1 = __float_as_uint(b_s[(kc + 4) * BST + n0]);
#pragma unroll
                for (int mt = 0; mt < 4; mt++)
                    MMA_TF32(acc[mt][nt], af[mt], b0, b1);
            }
        }
    }

#pragma unroll
    for (int mt = 0; mt < 4; mt++) {
#pragma unroll
        for (int nt = 0; nt < 8; nt++) {
            const int row0 = wm * 64 + mt * 16 + r;
            const int col  = wn * 64 + nt * 8 + 2 * c;
            *(float2*)(gC + (size_t)row0 * N + col) =
                make_float2(acc[mt][nt][0], acc[mt][nt][1]);
            *(float2*)(gC + (size_t)(row0 + 8) * N + col) =
                make_float2(acc[mt][nt][2], acc[mt][nt][3]);
        }
    }
}

// Wo GEMM
__global__ __launch_bounds__(256, 1) void tf32_gemm(
    const float* __restrict__ A, const float* __restrict__ B,
    float* __restrict__ C, int N, int K)
{
    extern __shared__ char smc[];
    const int bx = blockIdx.x, by = blockIdx.y;
    gemm_core(A + (size_t)(by * BMM) * K, B + bx * BNN,
              C + (size_t)(by * BMM) * N + bx * BNN, N, K, smc);
}

// fused QKV: grid.x = 16 (Q n-tiles) + 4 (K) + 4 (V), grid.y = M/256
__global__ __launch_bounds__(256, 1) void tf32_gemm_qkv(
    const float* __restrict__ x,
    const float* __restrict__ Wq, const float* __restrict__ Wk,
    const float* __restrict__ Wv,
    float* __restrict__ q, float* __restrict__ k, float* __restrict__ v)
{
    extern __shared__ char smc[];
    const int bx = blockIdx.x, by = blockIdx.y;
    const float* B;
    float* C;
    int N, xb;
    if (bx < 16)      { B = Wq; C = q; N = 2048; xb = bx; }
    else if (bx < 20) { B = Wk; C = k; N = 512;  xb = bx - 16; }
    else              { B = Wv; C = v; N = 512;  xb = bx - 20; }
    gemm_core(x + (size_t)(by * BMM) * DIN, B + xb * BNN,
              C + (size_t)(by * BMM) * N + xb * BNN, N, DIN, smc);
}

// ---------------- prep: rna-round x and weights into scratch ------------------
#define NX  ((size_t)NTOK * DIN)          // 8388608
#define NWQ ((size_t)DIN * DIN)           // 4194304
#define NWK ((size_t)DIN * 512)           // 1048576
__global__ __launch_bounds__(256) void round_all_kernel(
    const float* __restrict__ x,  const float* __restrict__ wq,
    const float* __restrict__ wk, const float* __restrict__ wv,
    const float* __restrict__ wo,
    float* __restrict__ xr,  float* __restrict__ wqr,
    float* __restrict__ wkr, float* __restrict__ wvr,
    float* __restrict__ wor)
{
    size_t i4 = ((size_t)blockIdx.x * 256 + threadIdx.x) * 4;
    const float* s;
    float* d;
    size_t off;
    if (i4 < NX)                         { s = x;  d = xr;  off = i4; }
    else if (i4 < NX + NWQ)              { s = wq; d = wqr; off = i4 - NX; }
    else if (i4 < NX + NWQ + NWK)        { s = wk; d = wkr; off = i4 - NX - NWQ; }
    else if (i4 < NX + NWQ + 2 * NWK)    { s = wv; d = wvr; off = i4 - NX - NWQ - NWK; }
    else                                 { s = wo; d = wor; off = i4 - NX - NWQ - 2 * NWK; }
    float4 v = *(const float4*)(s + off);
    float4 w;
    w.x = __uint_as_float(f2tf32(v.x));
    w.y = __uint_as_float(f2tf32(v.y));
    w.z = __uint_as_float(f2tf32(v.z));
    w.w = __uint_as_float(f2tf32(v.w));
    *(float4*)(d + off) = w;
}
#define ROUND_BLOCKS ((int)((NX + NWQ * 2 + NWK * 2) / (256 * 4)))   // 18432

// ---------------- fused RMSNorm + RoPE, q & k in one launch ------------------
__global__ __launch_bounds__(128) void rmsrope_kernel(
    float* __restrict__ q, float* __restrict__ k,
    const float* __restrict__ qw, const float* __restrict__ kw,
    const float* __restrict__ cosb, const float* __restrict__ sinb)
{
    const int tok = blockIdx.x;
    const int hy = blockIdx.y;
    const int d = threadIdx.x;
    const int s = tok & (SEQ - 1);

    float* p;
    const float* w;
    float outscale;
    if (hy < NH) {
        p = q + (size_t)tok * (NH * HD) + hy * HD;
        w = qw;
        outscale = QSCALE;
    } else {
        p = k + (size_t)tok * (NG * HD) + (hy - NH) * HD;
        w = kw;
        outscale = 1.0f;
    }
    float v = p[d];

    float ss = v * v;
#pragma unroll
    for (int o = 16; o > 0; o >>= 1) ss += __shfl_xor_sync(0xffffffffu, ss, o);

    __shared__ float partial[4];
    __shared__ float sn[HD];
    if ((d & 31) == 0) partial[d >> 5] = ss;
    __syncthreads();
    float tot = partial[0] + partial[1] + partial[2] + partial[3];
    float rstd = rsqrtf(tot * (1.0f / HD) + 1e-6f);

    float nv = v * rstd * w[d];
    sn[d] = nv;
    __syncthreads();
    float other = sn[d ^ 64];

    float cc = cosb[(size_t)s * HD + d];
    float si = sinb[(size_t)s * HD + d];
    float outv = (d < 64) ? (nv * cc - other * si) : (nv * cc + other * si);
    p[d] = outv * outscale;
}

// =============================================================================
// Tensor-core causal GQA flash attention (tf32 mma.sync). Epilogue emits
// tf32-rounded ctx so the Wo GEMM needs no in-loop conversion.
// =============================================================================
#define A_BQ 128
#define A_BK 64
#define QST 132
#define KST 132
#define VST 136
#define PST 68
#define SK_OFF (128 * QST)
#define SV_OFF (SK_OFF + 64 * KST)
#define SP_OFF (SV_OFF + 64 * VST)
#define ATTN_SMEM ((SP_OFF + 128 * PST) * 4)

__global__ __launch_bounds__(256, 1) void attn_tc_kernel(
    const float* __restrict__ q, const float* __restrict__ k,
    const float* __restrict__ v, float* __restrict__ out)
{
    extern __shared__ float smf[];
    float* sQ = smf;
    float* sK = smf + SK_OFF;
    float* sV = smf + SV_OFF;
    float* sP = smf + SP_OFF;

    const int tid  = threadIdx.x;
    const int wid  = tid >> 5;
    const int lane = tid & 31;
    const int r = lane >> 2;
    const int c = lane & 3;
    const int wm = wid;

    const int qt = gridDim.x - 1 - blockIdx.x;
    const int h  = blockIdx.y;
    const int b  = blockIdx.z;
    const int g  = h >> 2;
    const int qbase = qt * A_BQ;

    const float* qp = q + (size_t)b * SEQ * (NH * HD) + h * HD;
    const float* kp = k + (size_t)b * SEQ * (NG * HD) + g * HD;
    const float* vp = v + (size_t)b * SEQ * (NG * HD) + g * HD;

#pragma unroll
    for (int i = 0; i < 16; i++) {
        int idx = tid + i * 256;
        int row = idx >> 5, c4 = (idx & 31) * 4;
        float4 v4 = *(const float4*)(qp + (size_t)(qbase + row) * (NH * HD) + c4);
        float4 w4;
        w4.x = __uint_as_float(f2tf32(v4.x));
        w4.y = __uint_as_float(f2tf32(v4.y));
        w4.z = __uint_as_float(f2tf32(v4.z));
        w4.w = __uint_as_float(f2tf32(v4.w));
        *(float4*)(&sQ[row * QST + c4]) = w4;
    }

    float o[16][4];
#pragma unroll
    for (int nt = 0; nt < 16; nt++)
#pragma unroll
        for (int x = 0; x < 4; x++) o[nt][x] = 0.f;
    float m0 = -1e30f, m1 = -1e30f, l0 = 0.f, l1 = 0.f;

    const int row0g = qbase + wm * 16 + r;
    const int row1g = row0g + 8;

    const int ntiles = 2 * qt + 2;
    for (int kt = 0; kt < ntiles; kt++) {
        const int kbase = kt * A_BK;
        __syncthreads();
#pragma unroll
        for (int i = 0; i < 8; i++) {
            int idx = tid + i * 256;
            int row = idx >> 5, c4 = (idx & 31) * 4;
            float4 k4 = *(const float4*)(kp + (size_t)(kbase + row) * (NG * HD) + c4);
            float4 v4 = *(const float4*)(vp + (size_t)(kbase + row) * (NG * HD) + c4);
            float4 kw, vw;
            kw.x = __uint_as_float(f2tf32(k4.x));
            kw.y = __uint_as_float(f2tf32(k4.y));
            kw.z = __uint_as_float(f2tf32(k4.z));
            kw.w = __uint_as_float(f2tf32(k4.w));
            vw.x = __uint_as_float(f2tf32(v4.x));
            vw.y = __uint_as_float(f2tf32(v4.y));
            vw.z = __uint_as_float(f2tf32(v4.z));
            vw.w = __uint_as_float(f2tf32(v4.w));
            *(float4*)(&sK[row * KST + c4]) = kw;
            *(float4*)(&sV[row * VST + c4]) = vw;
        }
        __syncthreads();

        if (qbase + wm * 16 + 15 < kbase) continue;

        float sc[8][4];
#pragma unroll
        for (int nt = 0; nt < 8; nt++)
#pragma unroll
            for (int x = 0; x < 4; x++) sc[nt][x] = 0.f;

#pragma unroll
        for (int kk = 0; kk < 16; kk++) {
            const int kc = kk * 8 + c;
            uint32_t a[4];
            a[0] = __float_as_uint(sQ[(wm * 16 + r) * QST + kc]);
            a[1] = __float_as_uint(sQ[(wm * 16 + r + 8) * QST + kc]);
            a[2] = __float_as_uint(sQ[(wm * 16 + r) * QST + kc + 4]);
            a[3] = __float_as_uint(sQ[(wm * 16 + r + 8) * QST + kc + 4]);
#pragma unroll
            for (int nt = 0; nt < 8; nt++) {
                uint32_t b0 = __float_as_uint(sK[(nt * 8 + r) * KST + kc]);
                uint32_t b1 = __float_as_uint(sK[(nt * 8 + r) * KST + kc + 4]);
                MMA_TF32(sc[nt], a, b0, b1);
            }
        }

        if (kbase + 63 > qbase + wm * 16) {
#pragma unroll
            for (int nt = 0; nt < 8; nt++) {
                int col = kbase + nt * 8 + 2 * c;
                if (col     > row0g) sc[nt][0] = -1e30f;
                if (col + 1 > row0g) sc[nt][1] = -1e30f;
                if (col     > row1g) sc[nt][2] = -1e30f;
                if (col + 1 > row1g) sc[nt][3] = -1e30f;
            }
        }

        float tm0 = -1e30f, tm1 = -1e30f;
#pragma unroll
        for (int nt = 0; nt < 8; nt++) {
            tm0 = fmaxf(tm0, fmaxf(sc[nt][0], sc[nt][1]));
            tm1 = fmaxf(tm1, fmaxf(sc[nt][2], sc[nt][3]));
        }
        tm0 = fmaxf(tm0, __shfl_xor_sync(0xffffffffu, tm0, 1));
        tm0 = fmaxf(tm0, __shfl_xor_sync(0xffffffffu, tm0, 2));
        tm1 = fmaxf(tm1, __shfl_xor_sync(0xffffffffu, tm1, 1));
        tm1 = fmaxf(tm1, __shfl_xor_sync(0xffffffffu, tm1, 2));
        float nm0 = fmaxf(m0, tm0);
        float nm1 = fmaxf(m1, tm1);
        float al0 = __expf(m0 - nm0);
        float al1 = __expf(m1 - nm1);
        float ts0 = 0.f, ts1 = 0.f;
#pragma unroll
        for (int nt = 0; nt < 8; nt++) {
            sc[nt][0] = __expf(sc[nt][0] - nm0);
            sc[nt][1] = __expf(sc[nt][1] - nm0);
            sc[nt][2] = __expf(sc[nt][2] - nm1);
            sc[nt][3] = __expf(sc[nt][3] - nm1);
            ts0 += sc[nt][0] + sc[nt][1];
            ts1 += sc[nt][2] + sc[nt][3];
        }
        ts0 += __shfl_xor_sync(0xffffffffu, ts0, 1);
        ts0 += __shfl_xor_sync(0xffffffffu, ts0, 2);
        ts1 += __shfl_xor_sync(0xffffffffu, ts1, 1);
        ts1 += __shfl_xor_sync(0xffffffffu, ts1, 2);
        l0 = l0 * al0 + ts0;
        l1 = l1 * al1 + ts1;
        m0 = nm0;
        m1 = nm1;
#pragma unroll
        for (int nt = 0; nt < 16; nt++) {
            o[nt][0] *= al0;
            o[nt][1] *= al0;
            o[nt][2] *= al1;
            o[nt][3] *= al1;
        }

#pragma unroll
        for (int nt = 0; nt < 8; nt++) {
            *(float2*)(&sP[(wm * 16 + r) * PST + nt * 8 + 2 * c]) =
                make_float2(sc[nt][0], sc[nt][1]);
            *(float2*)(&sP[(wm * 16 + r + 8) * PST + nt * 8 + 2 * c]) =
                make_float2(sc[nt][2], sc[nt][3]);
        }
        __syncwarp();

#pragma unroll
        for (int kk = 0; kk < 8; kk++) {
            const int kc = kk * 8 + c;
            uint32_t pa[4];
            pa[0] = __float_as_uint(sP[(wm * 16 + r) * PST + kc]);
            pa[1] = __float_as_uint(sP[(wm * 16 + r + 8) * PST + kc]);
            pa[2] = __float_as_uint(sP[(wm * 16 + r) * PST + kc + 4]);
            pa[3] = __float_as_uint(sP[(wm * 16 + r + 8) * PST + kc + 4]);
#pragma unroll
            for (int nt = 0; nt < 16; nt++) {
                uint32_t b0 = __float_as_uint(sV[kc * VST + nt * 8 + r]);
                uint32_t b1 = __float_as_uint(sV[(kc + 4) * VST + nt * 8 + r]);
                MMA_TF32(o[nt], pa, b0, b1);
            }
        }
    }

    // epilogue: emit tf32-rounded ctx (Wo GEMM consumes raw bits via cp.async)
    const float inv0 = 1.0f / l0;
    const float inv1 = 1.0f / l1;
#pragma unroll
    for (int nt = 0; nt < 16; nt++) {
        const int col = h * HD + nt * 8 + 2 * c;
        float2 v0 = make_float2(
            __uint_as_float(f2tf32(o[nt][0] * inv0)),
            __uint_as_float(f2tf32(o[nt][1] * inv0)));
        float2 v1 = make_float2(
            __uint_as_float(f2tf32(o[nt][2] * inv1)),
            __uint_as_float(f2tf32(o[nt][3] * inv1)));
        *(float2*)(out + (size_t)((size_t)b * SEQ + row0g) * (NH * HD) + col) = v0;
        *(float2*)(out + (size_t)((size_t)b * SEQ + row1g) * (NH * HD) + col) = v1;
    }
}

// ---------------- launch -----------------------------------------------------
extern "C" void kernel_launch(void* const* d_in, const int* in_sizes, int n_in,
                              void* d_out, int out_size)
{
    const float* x    = (const float*)d_in[0];
    // d_in[1] = mask (causal, implicit)
    const float* cosb = (const float*)d_in[2];
    const float* sinb = (const float*)d_in[3];
    const float* Wq   = (const float*)d_in[4];
    const float* Wk   = (const float*)d_in[5];
    const float* Wv   = (const float*)d_in[6];
    const float* Wo   = (const float*)d_in[7];
    const float* qw   = (const float*)d_in[8];
    const float* kw   = (const float*)d_in[9];
    float* out = (float*)d_out;

    void *qp, *kp, *vp, *cp;
    void *xr, *wqr, *wkr, *wvr, *wor;
    cudaGetSymbolAddress(&qp, g_q);
    cudaGetSymbolAddress(&kp, g_k);
    cudaGetSymbolAddress(&vp, g_v);
    cudaGetSymbolAddress(&cp, g_ctx);
    cudaGetSymbolAddress(&xr, g_xr);
    cudaGetSymbolAddress(&wqr, g_wqr);
    cudaGetSymbolAddress(&wkr, g_wkr);
    cudaGetSymbolAddress(&wvr, g_wvr);
    cudaGetSymbolAddress(&wor, g_wor);

    cudaFuncSetAttribute(tf32_gemm, cudaFuncAttributeMaxDynamicSharedMemorySize, GEMM_SMEM);
    cudaFuncSetAttribute(tf32_gemm_qkv, cudaFuncAttributeMaxDynamicSharedMemorySize, GEMM_SMEM);
    cudaFuncSetAttribute(attn_tc_kernel, cudaFuncAttributeMaxDynamicSharedMemorySize, ATTN_SMEM);

    // prep: rna-round x + weights into scratch (one pass)
    round_all_kernel<<<ROUND_BLOCKS, 256>>>(
        x, Wq, Wk, Wv, Wo,
        (float*)xr, (float*)wqr, (float*)wkr, (float*)wvr, (float*)wor);

    // fused QKV projection
    tf32_gemm_qkv<<<dim3(24, NTOK / BMM), 256, GEMM_SMEM>>>(
        (const float*)xr, (const float*)wqr, (const float*)wkr, (const float*)wvr,
        (float*)qp, (float*)kp, (float*)vp);

    // fused RMSNorm + RoPE for q and k
    rmsrope_kernel<<<dim3(NTOK, NH + NG), 128>>>(
        (float*)qp, (float*)kp, qw, kw, cosb, sinb);

    // tensor-core flash attention (emits tf32-rounded ctx)
    attn_tc_kernel<<<dim3(SEQ / A_BQ, NH, 2), 256, ATTN_SMEM>>>(
        (const float*)qp, (const float*)kp, (const float*)vp, (float*)cp);

    // output projection
    tf32_gemm<<<dim3(DIN / BNN, NTOK / BMM), 256, GEMM_SMEM>>>(
        (const float*)cp, (const float*)wor, out, DIN, DIN);
}